// round 16
// baseline (speedup 1.0000x reference)
#include <cuda_runtime.h>
#include <cuda_fp16.h>
#include <cstdint>

#define N_NODES  10000
#define N_EDGES  640000
#define IN_FEAT  128
#define K_TOT    256
#define OUT_FEAT 256
#define CAP      160     // deg ~ Poisson(64); clamped

#define BUCKET_BLKS 313   // ceil(640000/(256*8))

// ---------------- device scratch ----------------
// g_deg starts zeroed (module load) and is re-zeroed by k_gemm_hN every launch.
__device__ __half g_A[N_NODES * K_TOT];      // [h | hN] fp16, row-major [row][k]
__device__ __half g_B[OUT_FEAT * K_TOT];     // W^T fp16, [n][k]
__device__ int g_deg[N_NODES];
__device__ int g_slots[N_NODES * CAP];

__device__ __forceinline__ int load_idx(const void* p, int e, int is64) {
    if (is64) return (int)((const long long*)p)[e];
    return ((const int*)p)[e];
}

// ================= bucket: 8 edges/thread, lane-interleaved =================
__global__ __launch_bounds__(256) void k_bucket(const void* srcp, const void* dstp) {
    int tid = threadIdx.x;
    __shared__ int s_not64;
    if (tid == 0) s_not64 = 0;
    __syncthreads();
    if (((const unsigned long long*)srcp)[tid] >= (unsigned long long)N_NODES)
        s_not64 = 1;
    __syncthreads();
    int is64 = !s_not64;

    int lane = tid & 31;
    int gwarp = blockIdx.x * 8 + (tid >> 5);
    int eBase = gwarp * 256 + lane;
    int s[8], d[8], pos[8];
    bool ok[8];
    #pragma unroll
    for (int i = 0; i < 8; i++) {
        int e = eBase + i * 32;
        ok[i] = (e < N_EDGES);
        if (ok[i]) {
            s[i] = load_idx(srcp, e, is64);
            d[i] = load_idx(dstp, e, is64);
        }
    }
    #pragma unroll
    for (int i = 0; i < 8; i++)
        if (ok[i]) pos[i] = atomicAdd(&g_deg[d[i]], 1);
    #pragma unroll
    for (int i = 0; i < 8; i++)
        if (ok[i] && pos[i] < CAP) g_slots[d[i] * CAP + pos[i]] = s[i];
}

// ================= prep: h -> A cols 0..127, W^T -> g_B =================
__global__ __launch_bounds__(256) void k_prep(const float* __restrict__ h,
                                              const float* __restrict__ W) {
    int t = blockIdx.x * 256 + threadIdx.x;
    int nt = gridDim.x * 256;
    for (int i = t; i < (N_NODES * IN_FEAT) / 4; i += nt) {
        float4 v = ((const float4*)h)[i];
        int row = i >> 5;
        int col = (i & 31) * 4;
        __half2* ap = (__half2*)(g_A + (size_t)row * K_TOT + col);
        ap[0] = __floats2half2_rn(v.x, v.y);
        ap[1] = __floats2half2_rn(v.z, v.w);
    }
    for (int i = t; i < K_TOT * OUT_FEAT; i += nt) {
        int k = i >> 8;
        int n = i & 255;
        g_B[(size_t)n * K_TOT + k] = __float2half_rn(W[(size_t)k * OUT_FEAT + n]);
    }
}

// ================= agg: mean over neighbors -> A cols 128..255 =================
__global__ __launch_bounds__(256) void k_agg() {
    int warp = (blockIdx.x * blockDim.x + threadIdx.x) >> 5;
    int lane = threadIdx.x & 31;
    if (warp >= N_NODES) return;
    int node = warp;
    int deg  = g_deg[node];
    int cnt  = min(deg, CAP);
    const int* slots = g_slots + node * CAP;

    float ax = 0.f, ay = 0.f, az = 0.f, aw = 0.f;
    int i = 0;
    for (; i + 8 <= cnt; i += 8) {
        int s[8];
        #pragma unroll
        for (int j = 0; j < 8; j++) s[j] = slots[i + j];
        uint2 r[8];
        #pragma unroll
        for (int j = 0; j < 8; j++)
            r[j] = ((const uint2*)(g_A + (size_t)s[j] * K_TOT))[lane];
        #pragma unroll
        for (int j = 0; j < 8; j++) {
            float2 lo = __half22float2(*(const __half2*)&r[j].x);
            float2 hi = __half22float2(*(const __half2*)&r[j].y);
            ax += lo.x; ay += lo.y; az += hi.x; aw += hi.y;
        }
    }
    for (; i < cnt; i++) {
        int s = slots[i];
        uint2 rr = ((const uint2*)(g_A + (size_t)s * K_TOT))[lane];
        float2 lo = __half22float2(*(const __half2*)&rr.x);
        float2 hi = __half22float2(*(const __half2*)&rr.y);
        ax += lo.x; ay += lo.y; az += hi.x; aw += hi.y;
    }
    float inv = (deg > 0) ? (1.0f / (float)deg) : 0.0f;
    __half2* ap = (__half2*)(g_A + (size_t)node * K_TOT + IN_FEAT + lane * 4);
    ap[0] = __floats2half2_rn(ax * inv, ay * inv);
    ap[1] = __floats2half2_rn(az * inv, aw * inv);
}

// ================= half-K GEMM pieces =================
// CTA tile M=64, N=128, K=128 resident. 8 warps 2(M)x4(N), warp tile 32x32.
// SSTRIDE=136 halves (68 words; 68 mod 32 = 4 -> banks (4g+t) conflict-free).
#define SSTRIDE 136
#define SA_HALVES (64 * SSTRIDE)
#define SB_HALVES (128 * SSTRIDE)
#define GEMM_SMEM ((SA_HALVES + SB_HALVES) * 2)   // 52224 B

#define MMA_F16(c, a, b)                                                     \
    asm volatile("mma.sync.aligned.m16n8k16.row.col.f32.f16.f16.f32 "        \
                 "{%0,%1,%2,%3}, {%4,%5,%6,%7}, {%8,%9}, {%0,%1,%2,%3};"     \
                 : "+f"((c)[0]), "+f"((c)[1]), "+f"((c)[2]), "+f"((c)[3])    \
                 : "r"((a)[0]), "r"((a)[1]), "r"((a)[2]), "r"((a)[3]),       \
                   "r"((b)[0]), "r"((b)[1]))

__device__ __forceinline__ void cp_async16(uint32_t smem_dst, const void* gsrc) {
    asm volatile("cp.async.cg.shared.global [%0], [%1], 16;"
                 :: "r"(smem_dst), "l"(gsrc) : "memory");
}

// kBase: 0 (self half) or 128 (hN half)
template<int KBASE, bool ADD>
__device__ __forceinline__ void gemm_body(const float* bias, float* C) {
    extern __shared__ __half smem[];
    __half* sA = smem;
    __half* sB = smem + SA_HALVES;

    int tid = threadIdx.x;
    int bx = blockIdx.x;               // n tile (0..1)
    int by = blockIdx.y;               // m tile (0..156)
    int rowBase = by * 64;
    int colBase = bx * 128;
    int wid = tid >> 5, lane = tid & 31;
    int g = lane >> 2, t = lane & 3;
    int wm = wid >> 2, wn = wid & 3;
    int rowW = wm * 32, colW = wn * 32;

    uint32_t sa_base = (uint32_t)__cvta_generic_to_shared(sA);
    uint32_t sb_base = (uint32_t)__cvta_generic_to_shared(sB);
    // A: 64 rows x 16 uint4 = 1024 -> 4/thread
    #pragma unroll
    for (int it = 0; it < 4; it++) {
        int idx = tid + it * 256;
        int row = idx >> 4, c = idx & 15;
        int gr = rowBase + row; if (gr >= N_NODES) gr = N_NODES - 1;
        cp_async16(sa_base + (uint32_t)(row * SSTRIDE + c * 8) * 2,
                   g_A + (size_t)gr * K_TOT + KBASE + c * 8);
    }
    // B: 128 rows x 16 uint4 = 2048 -> 8/thread
    #pragma unroll
    for (int it = 0; it < 8; it++) {
        int idx = tid + it * 256;
        int row = idx >> 4, c = idx & 15;
        cp_async16(sb_base + (uint32_t)(row * SSTRIDE + c * 8) * 2,
                   g_B + (size_t)(colBase + row) * K_TOT + KBASE + c * 8);
    }
    asm volatile("cp.async.commit_group;" ::: "memory");

    if (ADD) {
        // overlap: re-zero g_deg for next launch (314 blocks x 32 = 10048 >= 10000)
        int blin = by * 2 + bx;
        int z = blin * 32 + (tid & 31);
        if (tid < 32 && z < N_NODES) g_deg[z] = 0;
    }

    asm volatile("cp.async.wait_group 0;" ::: "memory");
    __syncthreads();

    float acc[2][4][4];
    #pragma unroll
    for (int mt = 0; mt < 2; mt++)
        #pragma unroll
        for (int ntl = 0; ntl < 4; ntl++)
            #pragma unroll
            for (int q = 0; q < 4; q++) acc[mt][ntl][q] = 0.f;

    #pragma unroll 4
    for (int ks = 0; ks < 8; ks++) {
        uint32_t afr[2][4];
        uint32_t bfr[4][2];
        #pragma unroll
        for (int mt = 0; mt < 2; mt++) {
            const __half* base = &sA[(rowW + mt * 16 + g) * SSTRIDE + ks * 16 + t * 2];
            afr[mt][0] = *(const uint32_t*)(base);
            afr[mt][1] = *(const uint32_t*)(base + 8 * SSTRIDE);
            afr[mt][2] = *(const uint32_t*)(base + 8);
            afr[mt][3] = *(const uint32_t*)(base + 8 * SSTRIDE + 8);
        }
        #pragma unroll
        for (int ntl = 0; ntl < 4; ntl++) {
            const __half* bb = &sB[(colW + ntl * 8 + g) * SSTRIDE + ks * 16 + t * 2];
            bfr[ntl][0] = *(const uint32_t*)(bb);
            bfr[ntl][1] = *(const uint32_t*)(bb + 8);
        }
        #pragma unroll
        for (int mt = 0; mt < 2; mt++)
            #pragma unroll
            for (int ntl = 0; ntl < 4; ntl++)
                MMA_F16(acc[mt][ntl], afr[mt], bfr[ntl]);
    }

    #pragma unroll
    for (int mt = 0; mt < 2; mt++) {
        int r0 = rowBase + rowW + mt * 16 + g;
        int r1 = r0 + 8;
        #pragma unroll
        for (int ntl = 0; ntl < 4; ntl++) {
            int col = colBase + colW + ntl * 8 + t * 2;
            if (ADD) {
                if (r0 < N_NODES) {
                    float2* p = (float2*)(C + (size_t)r0 * OUT_FEAT + col);
                    float2 cur = *p;
                    cur.x += acc[mt][ntl][0]; cur.y += acc[mt][ntl][1];
                    *p = cur;
                }
                if (r1 < N_NODES) {
                    float2* p = (float2*)(C + (size_t)r1 * OUT_FEAT + col);
                    float2 cur = *p;
                    cur.x += acc[mt][ntl][2]; cur.y += acc[mt][ntl][3];
                    *p = cur;
                }
            } else {
                float2 bv = *(const float2*)(bias + col);
                if (r0 < N_NODES) {
                    float2 v = make_float2(acc[mt][ntl][0] + bv.x, acc[mt][ntl][1] + bv.y);
                    *(float2*)(C + (size_t)r0 * OUT_FEAT + col) = v;
                }
                if (r1 < N_NODES) {
                    float2 v = make_float2(acc[mt][ntl][2] + bv.x, acc[mt][ntl][3] + bv.y);
                    *(float2*)(C + (size_t)r1 * OUT_FEAT + col) = v;
                }
            }
        }
    }
}

__global__ __launch_bounds__(256, 3) void k_gemm_self(const float* __restrict__ bias,
                                                      float* __restrict__ C) {
    gemm_body<0, false>(bias, C);
}
__global__ __launch_bounds__(256, 3) void k_gemm_hN(float* __restrict__ C) {
    gemm_body<IN_FEAT, true>(nullptr, C);
}

// ================= launch: two-stream fork/join =================
extern "C" void kernel_launch(void* const* d_in, const int* in_sizes, int n_in,
                              void* d_out, int out_size) {
    const float* h   = (const float*)d_in[0];
    const void*  src = d_in[1];
    const void*  dst = d_in[2];
    const float* W   = (const float*)d_in[3];
    const float* b   = (const float*)d_in[4];
    float* out = (float*)d_out;

    static cudaStream_t s2;
    static cudaEvent_t evFork, evPrep, evJoin;
    static int inited = 0;
    if (!inited) {
        cudaStreamCreateWithFlags(&s2, cudaStreamNonBlocking);
        cudaEventCreateWithFlags(&evFork, cudaEventDisableTiming);
        cudaEventCreateWithFlags(&evPrep, cudaEventDisableTiming);
        cudaEventCreateWithFlags(&evJoin, cudaEventDisableTiming);
        cudaFuncSetAttribute(k_gemm_self, cudaFuncAttributeMaxDynamicSharedMemorySize, GEMM_SMEM);
        cudaFuncSetAttribute(k_gemm_hN,  cudaFuncAttributeMaxDynamicSharedMemorySize, GEMM_SMEM);
        inited = 1;
    }

    dim3 ggrid(OUT_FEAT / 128, (N_NODES + 63) / 64);

    // fork: side stream runs bucket (independent of prep)
    cudaEventRecord(evFork, 0);
    cudaStreamWaitEvent(s2, evFork, 0);
    k_bucket<<<BUCKET_BLKS, 256, 0, s2>>>(src, dst);

    // main stream: prep, then self-half GEMM
    k_prep<<<160, 256>>>(h, W);
    cudaEventRecord(evPrep, 0);
    cudaStreamWaitEvent(s2, evPrep, 0);          // agg needs prep's A cols 0..127
    k_agg<<<(N_NODES * 32 + 255) / 256, 256, 0, s2>>>();
    cudaEventRecord(evJoin, s2);

    k_gemm_self<<<ggrid, 256, GEMM_SMEM>>>(b, out);

    // join: hN-half GEMM after agg and gemm_self
    cudaStreamWaitEvent(0, evJoin, 0);
    k_gemm_hN<<<ggrid, 256, GEMM_SMEM>>>(out);
}

// round 17
// speedup vs baseline: 1.0692x; 1.0692x over previous
#include <cuda_runtime.h>
#include <cuda_fp16.h>
#include <cstdint>

#define N_NODES  10000
#define N_EDGES  640000
#define IN_FEAT  128
#define K_TOT    256
#define OUT_FEAT 256
#define CAP      160     // deg ~ Poisson(64); clamped

#define BUCKET_WARPS (N_EDGES / 256)          // 2500, exact
#define BUCKET_BLKS  ((BUCKET_WARPS + 7) / 8) // 313
#define PREP_BLKS    160

// ---------------- device scratch ----------------
// g_deg starts zeroed (module load) and is re-zeroed by k_gemm every launch.
__device__ __half g_A[N_NODES * K_TOT];      // [h | hN] fp16, row-major [row][k]
__device__ __half g_B[OUT_FEAT * K_TOT];     // W^T fp16, [n][k]
__device__ int g_deg[N_NODES];
__device__ int g_slots[N_NODES * CAP];

// ================= kernel 1: fused bucket (first) + prep =================
__global__ __launch_bounds__(256) void k_prep_bucket(const void* srcp, const void* dstp,
                                                     const float* __restrict__ h,
                                                     const float* __restrict__ W) {
    int tid = threadIdx.x;
    if (blockIdx.x < BUCKET_BLKS) {
        // ---------- bucket: warp owns 256 consecutive edges; lane-striped vector loads ----------
        __shared__ int s_not64;
        if (tid == 0) s_not64 = 0;
        __syncthreads();
        if (((const unsigned long long*)srcp)[tid] >= (unsigned long long)N_NODES)
            s_not64 = 1;
        __syncthreads();
        int is64 = !s_not64;

        int lane  = tid & 31;
        int gwarp = blockIdx.x * 8 + (tid >> 5);
        if (gwarp >= BUCKET_WARPS) return;
        int warpBase = gwarp * 256;

        int s[8], d[8], pos[8];
        if (is64) {
            // lane loads longlong2 (2 edges); one warp instr covers 64 edges (1KB, 8 wf)
            #pragma unroll
            for (int i = 0; i < 4; i++) {
                int e = warpBase + 2 * lane + 64 * i;
                longlong2 vs = *(const longlong2*)((const long long*)srcp + e);
                longlong2 vd = *(const longlong2*)((const long long*)dstp + e);
                s[2 * i]     = (int)vs.x;  s[2 * i + 1] = (int)vs.y;
                d[2 * i]     = (int)vd.x;  d[2 * i + 1] = (int)vd.y;
            }
        } else {
            // lane loads int4 (4 edges); one warp instr covers 128 edges (512B, 4 wf)
            #pragma unroll
            for (int i = 0; i < 2; i++) {
                int e = warpBase + 4 * lane + 128 * i;
                int4 vs = *(const int4*)((const int*)srcp + e);
                int4 vd = *(const int4*)((const int*)dstp + e);
                s[4 * i] = vs.x; s[4 * i + 1] = vs.y; s[4 * i + 2] = vs.z; s[4 * i + 3] = vs.w;
                d[4 * i] = vd.x; d[4 * i + 1] = vd.y; d[4 * i + 2] = vd.z; d[4 * i + 3] = vd.w;
            }
        }
        #pragma unroll
        for (int i = 0; i < 8; i++) pos[i] = atomicAdd(&g_deg[d[i]], 1);
        #pragma unroll
        for (int i = 0; i < 8; i++)
            if (pos[i] < CAP) g_slots[d[i] * CAP + pos[i]] = s[i];
    } else {
        // ---------- prep ----------
        int t = (blockIdx.x - BUCKET_BLKS) * 256 + tid;
        int nt = PREP_BLKS * 256;
        // h -> A cols 0..127 (fp16)
        for (int i = t; i < (N_NODES * IN_FEAT) / 4; i += nt) {
            float4 v = ((const float4*)h)[i];
            int row = i >> 5;
            int col = (i & 31) * 4;
            __half2* ap = (__half2*)(g_A + (size_t)row * K_TOT + col);
            ap[0] = __floats2half2_rn(v.x, v.y);
            ap[1] = __floats2half2_rn(v.z, v.w);
        }
        // W^T fp16: B[n][k] = W[k][n]
        for (int i = t; i < K_TOT * OUT_FEAT; i += nt) {
            int k = i >> 8;
            int n = i & 255;
            g_B[(size_t)n * K_TOT + k] = __float2half_rn(W[(size_t)k * OUT_FEAT + n]);
        }
    }
}

// ================= kernel 2: mean-aggregate -> A cols 128..255 =================
__global__ __launch_bounds__(256) void k_agg() {
    int warp = (blockIdx.x * blockDim.x + threadIdx.x) >> 5;
    int lane = threadIdx.x & 31;
    if (warp >= N_NODES) return;
    int node = warp;
    int deg  = g_deg[node];
    int cnt  = min(deg, CAP);
    const int* slots = g_slots + node * CAP;

    float ax = 0.f, ay = 0.f, az = 0.f, aw = 0.f;
    int i = 0;
    for (; i + 8 <= cnt; i += 8) {
        int s[8];
        #pragma unroll
        for (int j = 0; j < 8; j++) s[j] = slots[i + j];
        uint2 r[8];
        #pragma unroll
        for (int j = 0; j < 8; j++)
            r[j] = ((const uint2*)(g_A + (size_t)s[j] * K_TOT))[lane];
        #pragma unroll
        for (int j = 0; j < 8; j++) {
            float2 lo = __half22float2(*(const __half2*)&r[j].x);
            float2 hi = __half22float2(*(const __half2*)&r[j].y);
            ax += lo.x; ay += lo.y; az += hi.x; aw += hi.y;
        }
    }
    for (; i < cnt; i++) {
        int s = slots[i];
        uint2 rr = ((const uint2*)(g_A + (size_t)s * K_TOT))[lane];
        float2 lo = __half22float2(*(const __half2*)&rr.x);
        float2 hi = __half22float2(*(const __half2*)&rr.y);
        ax += lo.x; ay += lo.y; az += hi.x; aw += hi.y;
    }
    float inv = (deg > 0) ? (1.0f / (float)deg) : 0.0f;
    __half2* ap = (__half2*)(g_A + (size_t)node * K_TOT + IN_FEAT + lane * 4);
    ap[0] = __floats2half2_rn(ax * inv, ay * inv);
    ap[1] = __floats2half2_rn(az * inv, aw * inv);
}

// ================= kernel 3: mma.sync fp16 GEMM, single-load smem-resident =================
// CTA tile M=64, N=128; K=256 resident. 8 warps 2(M)x4(N), warp tile 32x32.
// grid = 2 x 157 = 314; 2 CTAs/SM (203KB smem). Zero-barrier mainloop.
// Also re-zeroes g_deg for the next launch (nothing reads it after k_agg).
#define SSTRIDE 264
#define SA_HALVES (64 * SSTRIDE)
#define SB_HALVES (128 * SSTRIDE)
#define GEMM_SMEM ((SA_HALVES + SB_HALVES) * 2)

#define MMA_F16(c, a, b)                                                     \
    asm volatile("mma.sync.aligned.m16n8k16.row.col.f32.f16.f16.f32 "        \
                 "{%0,%1,%2,%3}, {%4,%5,%6,%7}, {%8,%9}, {%0,%1,%2,%3};"     \
                 : "+f"((c)[0]), "+f"((c)[1]), "+f"((c)[2]), "+f"((c)[3])    \
                 : "r"((a)[0]), "r"((a)[1]), "r"((a)[2]), "r"((a)[3]),       \
                   "r"((b)[0]), "r"((b)[1]))

__device__ __forceinline__ void cp_async16(uint32_t smem_dst, const void* gsrc) {
    asm volatile("cp.async.cg.shared.global [%0], [%1], 16;"
                 :: "r"(smem_dst), "l"(gsrc) : "memory");
}

__global__ __launch_bounds__(256, 2) void k_gemm(const float* __restrict__ bias,
                                                 float* __restrict__ C) {
    extern __shared__ __half smem[];
    __half* sA = smem;                 // [64][264]
    __half* sB = smem + SA_HALVES;     // [128][264]

    int tid = threadIdx.x;
    int bx = blockIdx.x;               // n tile (0..1)
    int by = blockIdx.y;               // m tile (0..156)
    int rowBase = by * 64;
    int colBase = bx * 128;
    int wid = tid >> 5, lane = tid & 31;
    int g = lane >> 2, t = lane & 3;
    int wm = wid >> 2, wn = wid & 3;
    int rowW = wm * 32, colW = wn * 32;

    // ---- bulk load: A 2048 uint4 (8/thread), B 4096 uint4 (16/thread) ----
    uint32_t sa_base = (uint32_t)__cvta_generic_to_shared(sA);
    uint32_t sb_base = (uint32_t)__cvta_generic_to_shared(sB);
    #pragma unroll
    for (int it = 0; it < 8; it++) {
        int idx = tid + it * 256;
        int row = idx >> 5, c = idx & 31;      // k = c*8
        int gr = rowBase + row; if (gr >= N_NODES) gr = N_NODES - 1;
        cp_async16(sa_base + (uint32_t)(row * SSTRIDE + c * 8) * 2,
                   g_A + (size_t)gr * K_TOT + c * 8);
    }
    #pragma unroll
    for (int it = 0; it < 16; it++) {
        int idx = tid + it * 256;
        int row = idx >> 5, c = idx & 31;
        cp_async16(sb_base + (uint32_t)(row * SSTRIDE + c * 8) * 2,
                   g_B + (size_t)(colBase + row) * K_TOT + c * 8);
    }
    asm volatile("cp.async.commit_group;" ::: "memory");

    // overlap: re-zero g_deg for next launch (314 blocks x 32 = 10048 >= 10000)
    {
        int blin = by * 2 + bx;
        int z = blin * 32 + (tid & 31);
        if (tid < 32 && z < N_NODES) g_deg[z] = 0;
    }

    asm volatile("cp.async.wait_group 0;" ::: "memory");
    __syncthreads();

    float acc[2][4][4];
    #pragma unroll
    for (int mt = 0; mt < 2; mt++)
        #pragma unroll
        for (int ntl = 0; ntl < 4; ntl++)
            #pragma unroll
            for (int q = 0; q < 4; q++) acc[mt][ntl][q] = 0.f;

    // ---- 16 ksteps, no barriers, full ILP ----
    #pragma unroll 4
    for (int ks = 0; ks < 16; ks++) {
        uint32_t afr[2][4];
        uint32_t bfr[4][2];
        #pragma unroll
        for (int mt = 0; mt < 2; mt++) {
            const __half* base = &sA[(rowW + mt * 16 + g) * SSTRIDE + ks * 16 + t * 2];
            afr[mt][0] = *(const uint32_t*)(base);
            afr[mt][1] = *(const uint32_t*)(base + 8 * SSTRIDE);   // row + 8
            afr[mt][2] = *(const uint32_t*)(base + 8);             // k + 8
            afr[mt][3] = *(const uint32_t*)(base + 8 * SSTRIDE + 8);
        }
        #pragma unroll
        for (int ntl = 0; ntl < 4; ntl++) {
            const __half* bb = &sB[(colW + ntl * 8 + g) * SSTRIDE + ks * 16 + t * 2];
            bfr[ntl][0] = *(const uint32_t*)(bb);
            bfr[ntl][1] = *(const uint32_t*)(bb + 8);
        }
        #pragma unroll
        for (int mt = 0; mt < 2; mt++)
            #pragma unroll
            for (int ntl = 0; ntl < 4; ntl++)
                MMA_F16(acc[mt][ntl], afr[mt], bfr[ntl]);
    }

    // ---- epilogue ----
    #pragma unroll
    for (int mt = 0; mt < 2; mt++) {
        int r0 = rowBase + rowW + mt * 16 + g;
        int r1 = r0 + 8;
        #pragma unroll
        for (int ntl = 0; ntl < 4; ntl++) {
            int col = colBase + colW + ntl * 8 + t * 2;
            float2 bv = *(const float2*)(bias + col);
            if (r0 < N_NODES) {
                float2 v = make_float2(acc[mt][ntl][0] + bv.x, acc[mt][ntl][1] + bv.y);
                *(float2*)(C + (size_t)r0 * OUT_FEAT + col) = v;
            }
            if (r1 < N_NODES) {
                float2 v = make_float2(acc[mt][ntl][2] + bv.x, acc[mt][ntl][3] + bv.y);
                *(float2*)(C + (size_t)r1 * OUT_FEAT + col) = v;
            }
        }
    }
}

// ================= launch =================
extern "C" void kernel_launch(void* const* d_in, const int* in_sizes, int n_in,
                              void* d_out, int out_size) {
    const float* h   = (const float*)d_in[0];
    const void*  src = d_in[1];
    const void*  dst = d_in[2];
    const float* W   = (const float*)d_in[3];
    const float* b   = (const float*)d_in[4];
    float* out = (float*)d_out;

    static int smem_set = 0;
    if (!smem_set) {
        cudaFuncSetAttribute(k_gemm, cudaFuncAttributeMaxDynamicSharedMemorySize, GEMM_SMEM);
        smem_set = 1;
    }

    k_prep_bucket<<<BUCKET_BLKS + PREP_BLKS, 256>>>(src, dst, h, W);
    k_agg<<<(N_NODES * 32 + 255) / 256, 256>>>();
    dim3 grid(OUT_FEAT / 128, (N_NODES + 63) / 64);
    k_gemm<<<grid, 256, GEMM_SMEM>>>(b, out);
}